// round 1
// baseline (speedup 1.0000x reference)
#include <cuda_runtime.h>

// Problem constants
constexpr int B_   = 2;
constexpr int SQ_  = 2048;
constexpr int SKV_ = 2048;
constexpr int H_   = 1024;
constexpr int NH_  = 16;
constexpr int HD_  = 64;

// Scratch (device globals: allocation-free, allowed)
__device__ float g_q[(size_t)B_ * SQ_ * H_];
__device__ float g_k[(size_t)B_ * SKV_ * H_];
__device__ float g_v[(size_t)B_ * SKV_ * H_];
__device__ float g_ctx[(size_t)B_ * SQ_ * H_];

// ---------------------------------------------------------------------------
// C[M,N] = A[M,K] @ W[N,K]^T (+ bias)   — torch Linear semantics
// 64x64 block tile, 256 threads, 4x4 microtile/thread, k-tile 16
// ---------------------------------------------------------------------------
__global__ __launch_bounds__(256) void sgemm_nt(
    const float* __restrict__ A, const float* __restrict__ W,
    const float* __restrict__ bias, float* __restrict__ C,
    int M, int N, int K)
{
    __shared__ float As[16][68];   // [k][m], pad 68 -> conflict-light
    __shared__ float Ws[16][68];   // [k][n]

    const int tid = threadIdx.x;
    const int tx = tid & 15, ty = tid >> 4;
    const int m0 = blockIdx.y << 6, n0 = blockIdx.x << 6;
    const int lrow = tid >> 2;          // 0..63
    const int lq   = (tid & 3) << 2;    // 0,4,8,12

    const float* Ap = A + (size_t)(m0 + lrow) * K + lq;
    const float* Wp = W + (size_t)(n0 + lrow) * K + lq;

    float acc[4][4] = {};
    float4 av = *(const float4*)Ap;
    float4 wv = *(const float4*)Wp;

    for (int k0 = 0; k0 < K; k0 += 16) {
        __syncthreads();
        As[lq+0][lrow] = av.x; As[lq+1][lrow] = av.y;
        As[lq+2][lrow] = av.z; As[lq+3][lrow] = av.w;
        Ws[lq+0][lrow] = wv.x; Ws[lq+1][lrow] = wv.y;
        Ws[lq+2][lrow] = wv.z; Ws[lq+3][lrow] = wv.w;
        if (k0 + 16 < K) {  // prefetch next k-tile into registers
            av = *(const float4*)(Ap + k0 + 16);
            wv = *(const float4*)(Wp + k0 + 16);
        }
        __syncthreads();
        #pragma unroll
        for (int kk = 0; kk < 16; kk++) {
            const float4 a = *(const float4*)&As[kk][ty << 2];
            const float4 b = *(const float4*)&Ws[kk][tx << 2];
            acc[0][0] += a.x*b.x; acc[0][1] += a.x*b.y; acc[0][2] += a.x*b.z; acc[0][3] += a.x*b.w;
            acc[1][0] += a.y*b.x; acc[1][1] += a.y*b.y; acc[1][2] += a.y*b.z; acc[1][3] += a.y*b.w;
            acc[2][0] += a.z*b.x; acc[2][1] += a.z*b.y; acc[2][2] += a.z*b.z; acc[2][3] += a.z*b.w;
            acc[3][0] += a.w*b.x; acc[3][1] += a.w*b.y; acc[3][2] += a.w*b.z; acc[3][3] += a.w*b.w;
        }
    }

    float4 bvv = make_float4(0.f, 0.f, 0.f, 0.f);
    if (bias) bvv = *(const float4*)(bias + n0 + (tx << 2));
    #pragma unroll
    for (int i = 0; i < 4; i++) {
        float4 w;
        w.x = acc[i][0] + bvv.x; w.y = acc[i][1] + bvv.y;
        w.z = acc[i][2] + bvv.z; w.w = acc[i][3] + bvv.w;
        *(float4*)(C + (size_t)(m0 + (ty << 2) + i) * N + n0 + (tx << 2)) = w;
    }
}

// ---------------------------------------------------------------------------
// Fused flash attention. One CTA = (batch b, head h, 64-row Q tile).
// Online softmax over 32 KV tiles of 64. Scores never touch HBM.
// Smem (dynamic, ~72.8 KB): Qt/Kt/Vs/Pt [64][68] + reductions.
// ---------------------------------------------------------------------------
__global__ __launch_bounds__(256) void flash_kernel(const float* __restrict__ mask)
{
    extern __shared__ float sm[];
    float (*Qt)[68] = (float(*)[68])sm;          // [d][r], pre-scaled by 1/8
    float (*Kt)[68] = Qt + 64;                   // [d][c]
    float (*Vs)[68] = Kt + 64;                   // [c][e]
    float (*Pt)[68] = Vs + 64;                   // [c][r]  (exp'd probs, transposed)
    float (*red)[64] = (float(*)[64])(Pt + 64);  // [16][64] partial max / partial sum
    float* sm_m  = (float*)(red + 16);
    float* sm_l  = sm_m + 64;
    float* sm_al = sm_l + 64;

    const int tid = threadIdx.x;
    const int tx = tid & 15, ty = tid >> 4;
    const int q0 = blockIdx.x << 6;
    const int h  = blockIdx.y;
    const int b  = blockIdx.z;

    const float* Qg = g_q + (size_t)(b * SQ_ + q0) * H_ + h * HD_;
    const float* Kg = g_k + (size_t)b * SKV_ * H_ + h * HD_;
    const float* Vg = g_v + (size_t)b * SKV_ * H_ + h * HD_;
    const float* Mg = mask + (size_t)(b * SQ_ + q0) * SKV_;

    // Load Q tile transposed, apply softmax scale 1/sqrt(64)
    #pragma unroll
    for (int it = 0; it < 4; it++) {
        const int i = tid + it * 256;
        const int r = i >> 4, q4 = (i & 15) << 2;
        const float4 v = *(const float4*)(Qg + (size_t)r * H_ + q4);
        Qt[q4+0][r] = v.x * 0.125f; Qt[q4+1][r] = v.y * 0.125f;
        Qt[q4+2][r] = v.z * 0.125f; Qt[q4+3][r] = v.w * 0.125f;
    }
    if (tid < 64) { sm_m[tid] = -1e30f; sm_l[tid] = 0.f; }

    float o[4][4] = {};

    for (int kv0 = 0; kv0 < SKV_; kv0 += 64) {
        __syncthreads();   // protects Kt/Vs/Pt reuse + Q/init on first iter
        #pragma unroll
        for (int it = 0; it < 4; it++) {
            const int i = tid + it * 256;
            const int c = i >> 4, q4 = (i & 15) << 2;
            const float4 kv = *(const float4*)(Kg + (size_t)(kv0 + c) * H_ + q4);
            Kt[q4+0][c] = kv.x; Kt[q4+1][c] = kv.y;
            Kt[q4+2][c] = kv.z; Kt[q4+3][c] = kv.w;
            *(float4*)&Vs[c][q4] = *(const float4*)(Vg + (size_t)(kv0 + c) * H_ + q4);
        }
        __syncthreads();

        // GEMM1: S = (Q*scale) @ K^T   (rows ty*4+i, cols tx*4+j)
        float s[4][4] = {};
        #pragma unroll 16
        for (int d = 0; d < 64; d++) {
            const float4 a  = *(const float4*)&Qt[d][ty << 2];
            const float4 k4 = *(const float4*)&Kt[d][tx << 2];
            s[0][0] += a.x*k4.x; s[0][1] += a.x*k4.y; s[0][2] += a.x*k4.z; s[0][3] += a.x*k4.w;
            s[1][0] += a.y*k4.x; s[1][1] += a.y*k4.y; s[1][2] += a.y*k4.z; s[1][3] += a.y*k4.w;
            s[2][0] += a.z*k4.x; s[2][1] += a.z*k4.y; s[2][2] += a.z*k4.z; s[2][3] += a.z*k4.w;
            s[3][0] += a.w*k4.x; s[3][1] += a.w*k4.y; s[3][2] += a.w*k4.z; s[3][3] += a.w*k4.w;
        }

        // additive mask + per-thread row-max partials
        #pragma unroll
        for (int i = 0; i < 4; i++) {
            const float4 mv = *(const float4*)(Mg + (size_t)((ty << 2) + i) * SKV_ + kv0 + (tx << 2));
            s[i][0] += (mv.x - 1.f) * 10000.f;
            s[i][1] += (mv.y - 1.f) * 10000.f;
            s[i][2] += (mv.z - 1.f) * 10000.f;
            s[i][3] += (mv.w - 1.f) * 10000.f;
            red[tx][(ty << 2) + i] = fmaxf(fmaxf(s[i][0], s[i][1]), fmaxf(s[i][2], s[i][3]));
        }
        __syncthreads();

        // per-row: new running max + rescale factor
        if (tid < 64) {
            float tm = red[0][tid];
            #pragma unroll
            for (int j = 1; j < 16; j++) tm = fmaxf(tm, red[j][tid]);
            const float mold = sm_m[tid];
            const float mnew = fmaxf(mold, tm);
            sm_al[tid] = __expf(mold - mnew);
            sm_m[tid]  = mnew;
        }
        __syncthreads();

        // exponentiate in-register, write P^T, accumulate partial row sums,
        // rescale O accumulators
        #pragma unroll
        for (int i = 0; i < 4; i++) {
            const int r = (ty << 2) + i;
            const float mnew = sm_m[r];
            const float al   = sm_al[r];
            float ps = 0.f;
            #pragma unroll
            for (int j = 0; j < 4; j++) {
                const float p = __expf(s[i][j] - mnew);
                Pt[(tx << 2) + j][r] = p;
                ps += p;
                o[i][j] *= al;
            }
            red[tx][r] = ps;
        }
        __syncthreads();

        // running denominator (64 threads) — concurrent with GEMM2 start below
        if (tid < 64) {
            float ssum = 0.f;
            #pragma unroll
            for (int j = 0; j < 16; j++) ssum += red[j][tid];
            sm_l[tid] = sm_l[tid] * sm_al[tid] + ssum;
        }

        // GEMM2: O += P @ V   (rows ty*4+i, head-dim cols tx*4+j)
        #pragma unroll 16
        for (int c = 0; c < 64; c++) {
            const float4 p  = *(const float4*)&Pt[c][ty << 2];
            const float4 vv = *(const float4*)&Vs[c][tx << 2];
            o[0][0] += p.x*vv.x; o[0][1] += p.x*vv.y; o[0][2] += p.x*vv.z; o[0][3] += p.x*vv.w;
            o[1][0] += p.y*vv.x; o[1][1] += p.y*vv.y; o[1][2] += p.y*vv.z; o[1][3] += p.y*vv.w;
            o[2][0] += p.z*vv.x; o[2][1] += p.z*vv.y; o[2][2] += p.z*vv.z; o[2][3] += p.z*vv.w;
            o[3][0] += p.w*vv.x; o[3][1] += p.w*vv.y; o[3][2] += p.w*vv.z; o[3][3] += p.w*vv.w;
        }
    }
    __syncthreads();  // make final sm_l visible

    float* Og = g_ctx + (size_t)(b * SQ_ + q0) * H_ + h * HD_;
    #pragma unroll
    for (int i = 0; i < 4; i++) {
        const float inv = 1.f / sm_l[(ty << 2) + i];
        const float4 w = make_float4(o[i][0]*inv, o[i][1]*inv, o[i][2]*inv, o[i][3]*inv);
        *(float4*)(Og + (size_t)((ty << 2) + i) * H_ + (tx << 2)) = w;
    }
}

// ---------------------------------------------------------------------------
extern "C" void kernel_launch(void* const* d_in, const int* in_sizes, int n_in,
                              void* d_out, int out_size)
{
    const float* xq  = (const float*)d_in[0];  // query_states   [B,SQ,H]
    const float* xkv = (const float*)d_in[1];  // key_value_states [B,SKV,H]
    const float* msk = (const float*)d_in[2];  // attention_mask [B,SQ,SKV]
    const float* Wq  = (const float*)d_in[3];
    const float* bq  = (const float*)d_in[4];
    const float* Wk  = (const float*)d_in[5];
    const float* Wv  = (const float*)d_in[6];
    const float* bv  = (const float*)d_in[7];
    const float* Wo  = (const float*)d_in[8];
    const float* bo  = (const float*)d_in[9];
    float* out = (float*)d_out;

    void *pq, *pk, *pv, *pc;
    cudaGetSymbolAddress(&pq, g_q);
    cudaGetSymbolAddress(&pk, g_k);
    cudaGetSymbolAddress(&pv, g_v);
    cudaGetSymbolAddress(&pc, g_ctx);

    const dim3 blk(256);
    const dim3 gproj(H_ / 64, (B_ * SQ_) / 64);  // (16, 64)

    // Projections (key proj has no bias, per reference)
    sgemm_nt<<<gproj, blk>>>(xq,  Wq, bq,      (float*)pq, B_ * SQ_,  H_, H_);
    sgemm_nt<<<gproj, blk>>>(xkv, Wk, nullptr, (float*)pk, B_ * SKV_, H_, H_);
    sgemm_nt<<<gproj, blk>>>(xkv, Wv, bv,      (float*)pv, B_ * SKV_, H_, H_);

    // Fused attention
    const int smem_bytes = (4 * 64 * 68 + 16 * 64 + 3 * 64) * (int)sizeof(float); // 74496
    cudaFuncSetAttribute(flash_kernel, cudaFuncAttributeMaxDynamicSharedMemorySize, smem_bytes);
    flash_kernel<<<dim3(SQ_ / 64, NH_, B_), blk, smem_bytes>>>(msk);

    // Output projection straight into d_out
    sgemm_nt<<<gproj, blk>>>((const float*)pc, Wo, bo, out, B_ * SQ_, H_, H_);
}

// round 2
// speedup vs baseline: 1.5729x; 1.5729x over previous
#include <cuda_runtime.h>

constexpr int B_   = 2;
constexpr int SQ_  = 2048;
constexpr int SKV_ = 2048;
constexpr int H_   = 1024;
constexpr int NH_  = 16;
constexpr int HD_  = 64;

__device__ float g_q[(size_t)B_ * SQ_ * H_];
__device__ float g_k[(size_t)B_ * SKV_ * H_];
__device__ float g_v[(size_t)B_ * SKV_ * H_];
__device__ float g_ctx[(size_t)B_ * SQ_ * H_];

__device__ __forceinline__ unsigned f2tf(float f) {
    unsigned u; asm("cvt.rna.tf32.f32 %0, %1;" : "=r"(u) : "f"(f)); return u;
}

// D += A(16x8) * B(8x8), tf32 inputs, fp32 accum
__device__ __forceinline__ void mma8(float d[4], const unsigned a[4], const unsigned b[2]) {
    asm volatile(
        "mma.sync.aligned.m16n8k8.row.col.f32.tf32.tf32.f32 "
        "{%0,%1,%2,%3},{%4,%5,%6,%7},{%8,%9},{%0,%1,%2,%3};"
        : "+f"(d[0]), "+f"(d[1]), "+f"(d[2]), "+f"(d[3])
        : "r"(a[0]), "r"(a[1]), "r"(a[2]), "r"(a[3]), "r"(b[0]), "r"(b[1]));
}

// ---------------------------------------------------------------------------
// C[M,N] = A[M,K] @ W[N,K]^T (+bias).  128x128 tile, BK=16, double-buffered.
// 256 threads = 8 warps in 2(m) x 4(n); warp tile 64x32 (4x4 mma frags).
// ---------------------------------------------------------------------------
__device__ __forceinline__ void gemm_body(
    const float* __restrict__ A, const float* __restrict__ W,
    const float* __restrict__ bias, float* __restrict__ C,
    int M, int N, int K)
{
    __shared__ unsigned As[2][128][20];   // [m][k], pad 20 -> conflict-free frags
    __shared__ unsigned Bs[2][128][20];   // [n][k]

    const int tid = threadIdx.x;
    const int wid = tid >> 5, lane = tid & 31;
    const int g = lane >> 2, tg = lane & 3;
    const int wm = wid >> 2, wn = wid & 3;       // 2 x 4 warp grid
    const int m0 = blockIdx.y << 7, n0 = blockIdx.x << 7;
    const int lrow = tid >> 1;                   // 0..127
    const int lk   = (tid & 1) << 3;             // 0 or 8

    const float* Ap = A + (size_t)(m0 + lrow) * K + lk;
    const float* Wp = W + (size_t)(n0 + lrow) * K + lk;

    float acc[4][4][4] = {};

    float4 a0v = *(const float4*)Ap,       a1v = *(const float4*)(Ap + 4);
    float4 b0v = *(const float4*)Wp,       b1v = *(const float4*)(Wp + 4);

    // store tile 0
    {
        unsigned* ar = &As[0][lrow][lk];
        ar[0]=f2tf(a0v.x); ar[1]=f2tf(a0v.y); ar[2]=f2tf(a0v.z); ar[3]=f2tf(a0v.w);
        ar[4]=f2tf(a1v.x); ar[5]=f2tf(a1v.y); ar[6]=f2tf(a1v.z); ar[7]=f2tf(a1v.w);
        unsigned* br = &Bs[0][lrow][lk];
        br[0]=f2tf(b0v.x); br[1]=f2tf(b0v.y); br[2]=f2tf(b0v.z); br[3]=f2tf(b0v.w);
        br[4]=f2tf(b1v.x); br[5]=f2tf(b1v.y); br[6]=f2tf(b1v.z); br[7]=f2tf(b1v.w);
    }
    __syncthreads();

    const int NT = K >> 4;
    for (int kt = 0; kt < NT; kt++) {
        if (kt + 1 < NT) {   // issue global prefetch early
            const float* Ap2 = Ap + (kt + 1) * 16;
            const float* Wp2 = Wp + (kt + 1) * 16;
            a0v = *(const float4*)Ap2; a1v = *(const float4*)(Ap2 + 4);
            b0v = *(const float4*)Wp2; b1v = *(const float4*)(Wp2 + 4);
        }
        const int buf = kt & 1;
        #pragma unroll
        for (int ks = 0; ks < 2; ks++) {
            const int kk = ks << 3;
            unsigned bf[4][2];
            #pragma unroll
            for (int ni = 0; ni < 4; ni++) {
                const int col = (wn << 5) + (ni << 3) + g;
                bf[ni][0] = Bs[buf][col][kk + tg];
                bf[ni][1] = Bs[buf][col][kk + tg + 4];
            }
            #pragma unroll
            for (int mi = 0; mi < 4; mi++) {
                const int row = (wm << 6) + (mi << 4);
                unsigned af[4];
                af[0] = As[buf][row + g    ][kk + tg];
                af[1] = As[buf][row + g + 8][kk + tg];
                af[2] = As[buf][row + g    ][kk + tg + 4];
                af[3] = As[buf][row + g + 8][kk + tg + 4];
                #pragma unroll
                for (int ni = 0; ni < 4; ni++) mma8(acc[mi][ni], af, bf[ni]);
            }
        }
        if (kt + 1 < NT) {
            unsigned* ar = &As[buf ^ 1][lrow][lk];
            ar[0]=f2tf(a0v.x); ar[1]=f2tf(a0v.y); ar[2]=f2tf(a0v.z); ar[3]=f2tf(a0v.w);
            ar[4]=f2tf(a1v.x); ar[5]=f2tf(a1v.y); ar[6]=f2tf(a1v.z); ar[7]=f2tf(a1v.w);
            unsigned* br = &Bs[buf ^ 1][lrow][lk];
            br[0]=f2tf(b0v.x); br[1]=f2tf(b0v.y); br[2]=f2tf(b0v.z); br[3]=f2tf(b0v.w);
            br[4]=f2tf(b1v.x); br[5]=f2tf(b1v.y); br[6]=f2tf(b1v.z); br[7]=f2tf(b1v.w);
        }
        __syncthreads();
    }

    #pragma unroll
    for (int mi = 0; mi < 4; mi++) {
        const int r = m0 + (wm << 6) + (mi << 4) + g;
        #pragma unroll
        for (int ni = 0; ni < 4; ni++) {
            const int c = n0 + (wn << 5) + (ni << 3) + (tg << 1);
            float bx = 0.f, by = 0.f;
            if (bias) { bx = bias[c]; by = bias[c + 1]; }
            float2 v0 = make_float2(acc[mi][ni][0] + bx, acc[mi][ni][1] + by);
            float2 v1 = make_float2(acc[mi][ni][2] + bx, acc[mi][ni][3] + by);
            *(float2*)(C + (size_t)r * N + c)       = v0;
            *(float2*)(C + (size_t)(r + 8) * N + c) = v1;
        }
    }
}

// Fused Q/K/V projections: blockIdx.z selects which GEMM
__global__ __launch_bounds__(256) void qkv_proj(
    const float* __restrict__ xq, const float* __restrict__ xkv,
    const float* __restrict__ Wq, const float* __restrict__ bq,
    const float* __restrict__ Wk,
    const float* __restrict__ Wv, const float* __restrict__ bv,
    float* __restrict__ q, float* __restrict__ k, float* __restrict__ v)
{
    const int z = blockIdx.z;
    const float* A    = (z == 0) ? xq : xkv;
    const float* W    = (z == 0) ? Wq : (z == 1 ? Wk : Wv);
    const float* bias = (z == 0) ? bq : (z == 1 ? nullptr : bv);
    float* C          = (z == 0) ? q  : (z == 1 ? k  : v);
    gemm_body(A, W, bias, C, B_ * SQ_, H_, H_);
}

__global__ __launch_bounds__(256) void out_proj(
    const float* __restrict__ ctx, const float* __restrict__ Wo,
    const float* __restrict__ bo, float* __restrict__ out)
{
    gemm_body(ctx, Wo, bo, out, B_ * SQ_, H_, H_);
}

// ---------------------------------------------------------------------------
// Flash attention with tf32 mma. CTA = (64-row Q tile, head, batch).
// 8 warps: 4(m) x 2(n); warp S/O block = 16 rows x 32 cols.
// ---------------------------------------------------------------------------
__global__ __launch_bounds__(256) void flash_mma(const float* __restrict__ mask)
{
    extern __shared__ float smf[];
    unsigned (*Qs)[68] = (unsigned(*)[68])smf;       // [r][d], pre-scaled
    unsigned (*Ks)[68] = Qs + 64;                    // [c][d]
    unsigned (*Vs)[72] = (unsigned(*)[72])(Ks + 64); // [c][e], pad 72
    unsigned (*Ps)[68] = (unsigned(*)[68])(Vs + 64); // [r][c]
    float* redm  = (float*)(Ps + 64);                // [2][64]
    float* reds  = redm + 128;                       // [2][64]
    float* sm_m  = reds + 128;
    float* sm_l  = sm_m + 64;
    float* sm_al = sm_l + 64;

    const int tid = threadIdx.x, wid = tid >> 5, lane = tid & 31;
    const int g = lane >> 2, tg = lane & 3;
    const int wm = wid & 3, wn = wid >> 2;           // 4 x 2
    const int r0 = wm << 4;
    const int q0 = blockIdx.x << 6, h = blockIdx.y, b = blockIdx.z;

    const float* Qg = g_q + (size_t)(b * SQ_ + q0) * H_ + h * HD_;
    const float* Kg = g_k + (size_t)b * SKV_ * H_ + h * HD_;
    const float* Vg = g_v + (size_t)b * SKV_ * H_ + h * HD_;
    const float* Mg = mask + (size_t)(b * SQ_ + q0) * SKV_;

    #pragma unroll
    for (int it = 0; it < 4; it++) {
        const int i = tid + it * 256;
        const int r = i >> 4, d = (i & 15) << 2;
        const float4 v = *(const float4*)(Qg + (size_t)r * H_ + d);
        uint4 w = make_uint4(f2tf(v.x * 0.125f), f2tf(v.y * 0.125f),
                             f2tf(v.z * 0.125f), f2tf(v.w * 0.125f));
        *(uint4*)&Qs[r][d] = w;
    }
    if (tid < 64) { sm_m[tid] = -1e30f; sm_l[tid] = 0.f; }

    float o[4][4] = {};   // rows r0+g / r0+g+8, cols wn*32 + ni*8 + 2tg(+1)

    for (int kv0 = 0; kv0 < SKV_; kv0 += 64) {
        __syncthreads();
        #pragma unroll
        for (int it = 0; it < 4; it++) {
            const int i = tid + it * 256;
            const int c = i >> 4, d = (i & 15) << 2;
            const float4 kvv = *(const float4*)(Kg + (size_t)(kv0 + c) * H_ + d);
            *(uint4*)&Ks[c][d] = make_uint4(f2tf(kvv.x), f2tf(kvv.y), f2tf(kvv.z), f2tf(kvv.w));
            const float4 vv = *(const float4*)(Vg + (size_t)(kv0 + c) * H_ + d);
            *(uint4*)&Vs[c][d] = make_uint4(f2tf(vv.x), f2tf(vv.y), f2tf(vv.z), f2tf(vv.w));
        }
        __syncthreads();

        // S = (Q/8) @ K^T
        float s[4][4] = {};
        #pragma unroll
        for (int ks = 0; ks < 8; ks++) {
            const int kk = ks << 3;
            unsigned af[4];
            af[0] = Qs[r0 + g    ][kk + tg];
            af[1] = Qs[r0 + g + 8][kk + tg];
            af[2] = Qs[r0 + g    ][kk + tg + 4];
            af[3] = Qs[r0 + g + 8][kk + tg + 4];
            #pragma unroll
            for (int ni = 0; ni < 4; ni++) {
                const int c = (wn << 5) + (ni << 3) + g;
                unsigned bf[2] = { Ks[c][kk + tg], Ks[c][kk + tg + 4] };
                mma8(s[ni], af, bf);
            }
        }

        // mask + per-thread row maxima
        float m0 = -1e30f, m1 = -1e30f;
        #pragma unroll
        for (int ni = 0; ni < 4; ni++) {
            const int c = (wn << 5) + (ni << 3) + (tg << 1);
            const float2 mv0 = *(const float2*)(Mg + (size_t)(r0 + g) * SKV_ + kv0 + c);
            const float2 mv1 = *(const float2*)(Mg + (size_t)(r0 + g + 8) * SKV_ + kv0 + c);
            s[ni][0] += (mv0.x - 1.f) * 10000.f;
            s[ni][1] += (mv0.y - 1.f) * 10000.f;
            s[ni][2] += (mv1.x - 1.f) * 10000.f;
            s[ni][3] += (mv1.y - 1.f) * 10000.f;
            m0 = fmaxf(m0, fmaxf(s[ni][0], s[ni][1]));
            m1 = fmaxf(m1, fmaxf(s[ni][2], s[ni][3]));
        }
        m0 = fmaxf(m0, __shfl_xor_sync(~0u, m0, 1));
        m0 = fmaxf(m0, __shfl_xor_sync(~0u, m0, 2));
        m1 = fmaxf(m1, __shfl_xor_sync(~0u, m1, 1));
        m1 = fmaxf(m1, __shfl_xor_sync(~0u, m1, 2));
        if (tg == 0) { redm[(wn << 6) + r0 + g] = m0; redm[(wn << 6) + r0 + g + 8] = m1; }
        __syncthreads();

        if (tid < 64) {
            const float mn = fmaxf(sm_m[tid], fmaxf(redm[tid], redm[64 + tid]));
            sm_al[tid] = __expf(sm_m[tid] - mn);
            sm_m[tid]  = mn;
        }
        __syncthreads();

        const float mn0 = sm_m[r0 + g],  mn1 = sm_m[r0 + g + 8];
        const float al0 = sm_al[r0 + g], al1 = sm_al[r0 + g + 8];
        float ps0 = 0.f, ps1 = 0.f;
        #pragma unroll
        for (int ni = 0; ni < 4; ni++) {
            const int c = (wn << 5) + (ni << 3) + (tg << 1);
            const float p00 = __expf(s[ni][0] - mn0), p01 = __expf(s[ni][1] - mn0);
            const float p10 = __expf(s[ni][2] - mn1), p11 = __expf(s[ni][3] - mn1);
            ps0 += p00 + p01; ps1 += p10 + p11;
            Ps[r0 + g    ][c] = f2tf(p00); Ps[r0 + g    ][c + 1] = f2tf(p01);
            Ps[r0 + g + 8][c] = f2tf(p10); Ps[r0 + g + 8][c + 1] = f2tf(p11);
            o[ni][0] *= al0; o[ni][1] *= al0; o[ni][2] *= al1; o[ni][3] *= al1;
        }
        ps0 += __shfl_xor_sync(~0u, ps0, 1); ps0 += __shfl_xor_sync(~0u, ps0, 2);
        ps1 += __shfl_xor_sync(~0u, ps1, 1); ps1 += __shfl_xor_sync(~0u, ps1, 2);
        if (tg == 0) { reds[(wn << 6) + r0 + g] = ps0; reds[(wn << 6) + r0 + g + 8] = ps1; }
        __syncthreads();
        if (tid < 64) sm_l[tid] = sm_l[tid] * sm_al[tid] + reds[tid] + reds[64 + tid];

        // O += P @ V
        #pragma unroll
        for (int ks = 0; ks < 8; ks++) {
            const int kk = ks << 3;
            unsigned af[4];
            af[0] = Ps[r0 + g    ][kk + tg];
            af[1] = Ps[r0 + g + 8][kk + tg];
            af[2] = Ps[r0 + g    ][kk + tg + 4];
            af[3] = Ps[r0 + g + 8][kk + tg + 4];
            #pragma unroll
            for (int ni = 0; ni < 4; ni++) {
                const int e = (wn << 5) + (ni << 3) + g;
                unsigned bf[2] = { Vs[kk + tg][e], Vs[kk + tg + 4][e] };
                mma8(o[ni], af, bf);
            }
        }
    }
    __syncthreads();

    float* Og = g_ctx + (size_t)(b * SQ_ + q0) * H_ + h * HD_;
    const float inv0 = 1.f / sm_l[r0 + g], inv1 = 1.f / sm_l[r0 + g + 8];
    #pragma unroll
    for (int ni = 0; ni < 4; ni++) {
        const int c = (wn << 5) + (ni << 3) + (tg << 1);
        float2 v0 = make_float2(o[ni][0] * inv0, o[ni][1] * inv0);
        float2 v1 = make_float2(o[ni][2] * inv1, o[ni][3] * inv1);
        *(float2*)(Og + (size_t)(r0 + g) * H_ + c)     = v0;
        *(float2*)(Og + (size_t)(r0 + g + 8) * H_ + c) = v1;
    }
}

// ---------------------------------------------------------------------------
extern "C" void kernel_launch(void* const* d_in, const int* in_sizes, int n_in,
                              void* d_out, int out_size)
{
    const float* xq  = (const float*)d_in[0];
    const float* xkv = (const float*)d_in[1];
    const float* msk = (const float*)d_in[2];
    const float* Wq  = (const float*)d_in[3];
    const float* bq  = (const float*)d_in[4];
    const float* Wk  = (const float*)d_in[5];
    const float* Wv  = (const float*)d_in[6];
    const float* bv  = (const float*)d_in[7];
    const float* Wo  = (const float*)d_in[8];
    const float* bo  = (const float*)d_in[9];
    float* out = (float*)d_out;

    void *pq, *pk, *pv, *pc;
    cudaGetSymbolAddress(&pq, g_q);
    cudaGetSymbolAddress(&pk, g_k);
    cudaGetSymbolAddress(&pv, g_v);
    cudaGetSymbolAddress(&pc, g_ctx);

    const dim3 blk(256);

    qkv_proj<<<dim3(H_ / 128, (B_ * SQ_) / 128, 3), blk>>>(
        xq, xkv, Wq, bq, Wk, Wv, bv, (float*)pq, (float*)pk, (float*)pv);

    const int smem_bytes = (64 * 68 * 3 + 64 * 72 + 128 + 128 + 192) * (int)sizeof(float);
    cudaFuncSetAttribute(flash_mma, cudaFuncAttributeMaxDynamicSharedMemorySize, smem_bytes);
    flash_mma<<<dim3(SQ_ / 64, NH_, B_), blk, smem_bytes>>>(msk);

    out_proj<<<dim3(H_ / 128, (B_ * SQ_) / 128), blk>>>((const float*)pc, Wo, bo, out);
}

// round 3
// speedup vs baseline: 2.3915x; 1.5204x over previous
#include <cuda_runtime.h>

constexpr int B_   = 2;
constexpr int SQ_  = 2048;
constexpr int SKV_ = 2048;
constexpr int H_   = 1024;
constexpr int NH_  = 16;
constexpr int HD_  = 64;

__device__ float g_q[(size_t)B_ * SQ_ * H_];
__device__ float g_k[(size_t)B_ * SKV_ * H_];
__device__ float g_v[(size_t)B_ * SKV_ * H_];
__device__ float g_ctx[(size_t)B_ * SQ_ * H_];

__device__ __forceinline__ unsigned f2tf(float f) {
    unsigned u; asm("cvt.rna.tf32.f32 %0, %1;" : "=r"(u) : "f"(f)); return u;
}

// D += A(16x8) * B(8x8), tf32 inputs, fp32 accum
__device__ __forceinline__ void mma8(float d[4], const unsigned a[4], const unsigned b[2]) {
    asm volatile(
        "mma.sync.aligned.m16n8k8.row.col.f32.tf32.tf32.f32 "
        "{%0,%1,%2,%3},{%4,%5,%6,%7},{%8,%9},{%0,%1,%2,%3};"
        : "+f"(d[0]), "+f"(d[1]), "+f"(d[2]), "+f"(d[3])
        : "r"(a[0]), "r"(a[1]), "r"(a[2]), "r"(a[3]), "r"(b[0]), "r"(b[1]));
}

// ---------------------------------------------------------------------------
// C[M,N] = A[M,K] @ W[N,K]^T (+bias).  128x128 tile, BK=16, double-buffered.
// 256 threads = 8 warps in 2(m) x 4(n); warp tile 64x32 (4x4 mma frags).
// ---------------------------------------------------------------------------
__device__ __forceinline__ void gemm_body(
    const float* __restrict__ A, const float* __restrict__ W,
    const float* __restrict__ bias, float* __restrict__ C,
    int M, int N, int K)
{
    __shared__ unsigned As[2][128][20];   // [m][k], pad 20 -> conflict-free frags
    __shared__ unsigned Bs[2][128][20];   // [n][k]

    const int tid = threadIdx.x;
    const int wid = tid >> 5, lane = tid & 31;
    const int g = lane >> 2, tg = lane & 3;
    const int wm = wid >> 2, wn = wid & 3;       // 2 x 4 warp grid
    const int m0 = blockIdx.y << 7, n0 = blockIdx.x << 7;
    const int lrow = tid >> 1;                   // 0..127
    const int lk   = (tid & 1) << 3;             // 0 or 8

    const float* Ap = A + (size_t)(m0 + lrow) * K + lk;
    const float* Wp = W + (size_t)(n0 + lrow) * K + lk;

    float acc[4][4][4] = {};

    float4 a0v = *(const float4*)Ap,       a1v = *(const float4*)(Ap + 4);
    float4 b0v = *(const float4*)Wp,       b1v = *(const float4*)(Wp + 4);

    // store tile 0
    {
        unsigned* ar = &As[0][lrow][lk];
        ar[0]=f2tf(a0v.x); ar[1]=f2tf(a0v.y); ar[2]=f2tf(a0v.z); ar[3]=f2tf(a0v.w);
        ar[4]=f2tf(a1v.x); ar[5]=f2tf(a1v.y); ar[6]=f2tf(a1v.z); ar[7]=f2tf(a1v.w);
        unsigned* br = &Bs[0][lrow][lk];
        br[0]=f2tf(b0v.x); br[1]=f2tf(b0v.y); br[2]=f2tf(b0v.z); br[3]=f2tf(b0v.w);
        br[4]=f2tf(b1v.x); br[5]=f2tf(b1v.y); br[6]=f2tf(b1v.z); br[7]=f2tf(b1v.w);
    }
    __syncthreads();

    const int NT = K >> 4;
    for (int kt = 0; kt < NT; kt++) {
        if (kt + 1 < NT) {   // issue global prefetch early
            const float* Ap2 = Ap + (kt + 1) * 16;
            const float* Wp2 = Wp + (kt + 1) * 16;
            a0v = *(const float4*)Ap2; a1v = *(const float4*)(Ap2 + 4);
            b0v = *(const float4*)Wp2; b1v = *(const float4*)(Wp2 + 4);
        }
        const int buf = kt & 1;
        #pragma unroll
        for (int ks = 0; ks < 2; ks++) {
            const int kk = ks << 3;
            unsigned bf[4][2];
            #pragma unroll
            for (int ni = 0; ni < 4; ni++) {
                const int col = (wn << 5) + (ni << 3) + g;
                bf[ni][0] = Bs[buf][col][kk + tg];
                bf[ni][1] = Bs[buf][col][kk + tg + 4];
            }
            #pragma unroll
            for (int mi = 0; mi < 4; mi++) {
                const int row = (wm << 6) + (mi << 4);
                unsigned af[4];
                af[0] = As[buf][row + g    ][kk + tg];
                af[1] = As[buf][row + g + 8][kk + tg];
                af[2] = As[buf][row + g    ][kk + tg + 4];
                af[3] = As[buf][row + g + 8][kk + tg + 4];
                #pragma unroll
                for (int ni = 0; ni < 4; ni++) mma8(acc[mi][ni], af, bf[ni]);
            }
        }
        if (kt + 1 < NT) {
            unsigned* ar = &As[buf ^ 1][lrow][lk];
            ar[0]=f2tf(a0v.x); ar[1]=f2tf(a0v.y); ar[2]=f2tf(a0v.z); ar[3]=f2tf(a0v.w);
            ar[4]=f2tf(a1v.x); ar[5]=f2tf(a1v.y); ar[6]=f2tf(a1v.z); ar[7]=f2tf(a1v.w);
            unsigned* br = &Bs[buf ^ 1][lrow][lk];
            br[0]=f2tf(b0v.x); br[1]=f2tf(b0v.y); br[2]=f2tf(b0v.z); br[3]=f2tf(b0v.w);
            br[4]=f2tf(b1v.x); br[5]=f2tf(b1v.y); br[6]=f2tf(b1v.z); br[7]=f2tf(b1v.w);
        }
        __syncthreads();
    }

    #pragma unroll
    for (int mi = 0; mi < 4; mi++) {
        const int r = m0 + (wm << 6) + (mi << 4) + g;
        #pragma unroll
        for (int ni = 0; ni < 4; ni++) {
            const int c = n0 + (wn << 5) + (ni << 3) + (tg << 1);
            float bx = 0.f, by = 0.f;
            if (bias) { bx = bias[c]; by = bias[c + 1]; }
            float2 v0 = make_float2(acc[mi][ni][0] + bx, acc[mi][ni][1] + by);
            float2 v1 = make_float2(acc[mi][ni][2] + bx, acc[mi][ni][3] + by);
            *(float2*)(C + (size_t)r * N + c)       = v0;
            *(float2*)(C + (size_t)(r + 8) * N + c) = v1;
        }
    }
}

// Fused Q/K/V projections: blockIdx.z selects which GEMM
__global__ __launch_bounds__(256) void qkv_proj(
    const float* __restrict__ xq, const float* __restrict__ xkv,
    const float* __restrict__ Wq, const float* __restrict__ bq,
    const float* __restrict__ Wk,
    const float* __restrict__ Wv, const float* __restrict__ bv,
    float* __restrict__ q, float* __restrict__ k, float* __restrict__ v)
{
    const int z = blockIdx.z;
    const float* A    = (z == 0) ? xq : xkv;
    const float* W    = (z == 0) ? Wq : (z == 1 ? Wk : Wv);
    const float* bias = (z == 0) ? bq : (z == 1 ? nullptr : bv);
    float* C          = (z == 0) ? q  : (z == 1 ? k  : v);
    gemm_body(A, W, bias, C, B_ * SQ_, H_, H_);
}

__global__ __launch_bounds__(256) void out_proj(
    const float* __restrict__ ctx, const float* __restrict__ Wo,
    const float* __restrict__ bo, float* __restrict__ out)
{
    gemm_body(ctx, Wo, bo, out, B_ * SQ_, H_, H_);
}

// ---------------------------------------------------------------------------
// Flash attention with tf32 mma. CTA = (64-row Q tile, head, batch).
// 8 warps: 4(m) x 2(n); warp S/O block = 16 rows x 32 cols.
// ---------------------------------------------------------------------------
__global__ __launch_bounds__(256) void flash_mma(const float* __restrict__ mask)
{
    extern __shared__ float smf[];
    unsigned (*Qs)[68] = (unsigned(*)[68])smf;       // [r][d], pre-scaled
    unsigned (*Ks)[68] = Qs + 64;                    // [c][d]
    unsigned (*Vs)[72] = (unsigned(*)[72])(Ks + 64); // [c][e], pad 72
    unsigned (*Ps)[68] = (unsigned(*)[68])(Vs + 64); // [r][c]
    float* redm  = (float*)(Ps + 64);                // [2][64]
    float* reds  = redm + 128;                       // [2][64]
    float* sm_m  = reds + 128;
    float* sm_l  = sm_m + 64;
    float* sm_al = sm_l + 64;

    const int tid = threadIdx.x, wid = tid >> 5, lane = tid & 31;
    const int g = lane >> 2, tg = lane & 3;
    const int wm = wid & 3, wn = wid >> 2;           // 4 x 2
    const int r0 = wm << 4;
    const int q0 = blockIdx.x << 6, h = blockIdx.y, b = blockIdx.z;

    const float* Qg = g_q + (size_t)(b * SQ_ + q0) * H_ + h * HD_;
    const float* Kg = g_k + (size_t)b * SKV_ * H_ + h * HD_;
    const float* Vg = g_v + (size_t)b * SKV_ * H_ + h * HD_;
    const float* Mg = mask + (size_t)(b * SQ_ + q0) * SKV_;

    #pragma unroll
    for (int it = 0; it < 4; it++) {
        const int i = tid + it * 256;
        const int r = i >> 4, d = (i & 15) << 2;
        const float4 v = *(const float4*)(Qg + (size_t)r * H_ + d);
        uint4 w = make_uint4(f2tf(v.x * 0.125f), f2tf(v.y * 0.125f),
                             f2tf(v.z * 0.125f), f2tf(v.w * 0.125f));
        *(uint4*)&Qs[r][d] = w;
    }
    if (tid < 64) { sm_m[tid] = -1e30f; sm_l[tid] = 0.f; }

    float o[4][4] = {};   // rows r0+g / r0+g+8, cols wn*32 + ni*8 + 2tg(+1)

    for (int kv0 = 0; kv0 < SKV_; kv0 += 64) {
        __syncthreads();
        #pragma unroll
        for (int it = 0; it < 4; it++) {
            const int i = tid + it * 256;
            const int c = i >> 4, d = (i & 15) << 2;
            const float4 kvv = *(const float4*)(Kg + (size_t)(kv0 + c) * H_ + d);
            *(uint4*)&Ks[c][d] = make_uint4(f2tf(kvv.x), f2tf(kvv.y), f2tf(kvv.z), f2tf(kvv.w));
            const float4 vv = *(const float4*)(Vg + (size_t)(kv0 + c) * H_ + d);
            *(uint4*)&Vs[c][d] = make_uint4(f2tf(vv.x), f2tf(vv.y), f2tf(vv.z), f2tf(vv.w));
        }
        __syncthreads();

        // S = (Q/8) @ K^T
        float s[4][4] = {};
        #pragma unroll
        for (int ks = 0; ks < 8; ks++) {
            const int kk = ks << 3;
            unsigned af[4];
            af[0] = Qs[r0 + g    ][kk + tg];
            af[1] = Qs[r0 + g + 8][kk + tg];
            af[2] = Qs[r0 + g    ][kk + tg + 4];
            af[3] = Qs[r0 + g + 8][kk + tg + 4];
            #pragma unroll
            for (int ni = 0; ni < 4; ni++) {
                const int c = (wn << 5) + (ni << 3) + g;
                unsigned bf[2] = { Ks[c][kk + tg], Ks[c][kk + tg + 4] };
                mma8(s[ni], af, bf);
            }
        }

        // mask + per-thread row maxima
        float m0 = -1e30f, m1 = -1e30f;
        #pragma unroll
        for (int ni = 0; ni < 4; ni++) {
            const int c = (wn << 5) + (ni << 3) + (tg << 1);
            const float2 mv0 = *(const float2*)(Mg + (size_t)(r0 + g) * SKV_ + kv0 + c);
            const float2 mv1 = *(const float2*)(Mg + (size_t)(r0 + g + 8) * SKV_ + kv0 + c);
            s[ni][0] += (mv0.x - 1.f) * 10000.f;
            s[ni][1] += (mv0.y - 1.f) * 10000.f;
            s[ni][2] += (mv1.x - 1.f) * 10000.f;
            s[ni][3] += (mv1.y - 1.f) * 10000.f;
            m0 = fmaxf(m0, fmaxf(s[ni][0], s[ni][1]));
            m1 = fmaxf(m1, fmaxf(s[ni][2], s[ni][3]));
        }
        m0 = fmaxf(m0, __shfl_xor_sync(~0u, m0, 1));
        m0 = fmaxf(m0, __shfl_xor_sync(~0u, m0, 2));
        m1 = fmaxf(m1, __shfl_xor_sync(~0u, m1, 1));
        m1 = fmaxf(m1, __shfl_xor_sync(~0u, m1, 2));
        if (tg == 0) { redm[(wn << 6) + r0 + g] = m0; redm[(wn << 6) + r0 + g + 8] = m1; }
        __syncthreads();

        if (tid < 64) {
            const float mn = fmaxf(sm_m[tid], fmaxf(redm[tid], redm[64 + tid]));
            sm_al[tid] = __expf(sm_m[tid] - mn);
            sm_m[tid]  = mn;
        }
        __syncthreads();

        const float mn0 = sm_m[r0 + g],  mn1 = sm_m[r0 + g + 8];
        const float al0 = sm_al[r0 + g], al1 = sm_al[r0 + g + 8];
        float ps0 = 0.f, ps1 = 0.f;
        #pragma unroll
        for (int ni = 0; ni < 4; ni++) {
            const int c = (wn << 5) + (ni << 3) + (tg << 1);
            const float p00 = __expf(s[ni][0] - mn0), p01 = __expf(s[ni][1] - mn0);
            const float p10 = __expf(s[ni][2] - mn1), p11 = __expf(s[ni][3] - mn1);
            ps0 += p00 + p01; ps1 += p10 + p11;
            Ps[r0 + g    ][c] = f2tf(p00); Ps[r0 + g    ][c + 1] = f2tf(p01);
            Ps[r0 + g + 8][c] = f2tf(p10); Ps[r0 + g + 8][c + 1] = f2tf(p11);
            o[ni][0] *= al0; o[ni][1] *= al0; o[ni][2] *= al1; o[ni][3] *= al1;
        }
        ps0 += __shfl_xor_sync(~0u, ps0, 1); ps0 += __shfl_xor_sync(~0u, ps0, 2);
        ps1 += __shfl_xor_sync(~0u, ps1, 1); ps1 += __shfl_xor_sync(~0u, ps1, 2);
        if (tg == 0) { reds[(wn << 6) + r0 + g] = ps0; reds[(wn << 6) + r0 + g + 8] = ps1; }
        __syncthreads();
        if (tid < 64) sm_l[tid] = sm_l[tid] * sm_al[tid] + reds[tid] + reds[64 + tid];

        // O += P @ V
        #pragma unroll
        for (int ks = 0; ks < 8; ks++) {
            const int kk = ks << 3;
            unsigned af[4];
            af[0] = Ps[r0 + g    ][kk + tg];
            af[1] = Ps[r0 + g + 8][kk + tg];
            af[2] = Ps[r0 + g    ][kk + tg + 4];
            af[3] = Ps[r0 + g + 8][kk + tg + 4];
            #pragma unroll
            for (int ni = 0; ni < 4; ni++) {
                const int e = (wn << 5) + (ni << 3) + g;
                unsigned bf[2] = { Vs[kk + tg][e], Vs[kk + tg + 4][e] };
                mma8(o[ni], af, bf);
            }
        }
    }
    __syncthreads();

    float* Og = g_ctx + (size_t)(b * SQ_ + q0) * H_ + h * HD_;
    const float inv0 = 1.f / sm_l[r0 + g], inv1 = 1.f / sm_l[r0 + g + 8];
    #pragma unroll
    for (int ni = 0; ni < 4; ni++) {
        const int c = (wn << 5) + (ni << 3) + (tg << 1);
        float2 v0 = make_float2(o[ni][0] * inv0, o[ni][1] * inv0);
        float2 v1 = make_float2(o[ni][2] * inv1, o[ni][3] * inv1);
        *(float2*)(Og + (size_t)(r0 + g) * H_ + c)     = v0;
        *(float2*)(Og + (size_t)(r0 + g + 8) * H_ + c) = v1;
    }
}

// ---------------------------------------------------------------------------
extern "C" void kernel_launch(void* const* d_in, const int* in_sizes, int n_in,
                              void* d_out, int out_size)
{
    const float* xq  = (const float*)d_in[0];
    const float* xkv = (const float*)d_in[1];
    const float* msk = (const float*)d_in[2];
    const float* Wq  = (const float*)d_in[3];
    const float* bq  = (const float*)d_in[4];
    const float* Wk  = (const float*)d_in[5];
    const float* Wv  = (const float*)d_in[6];
    const float* bv  = (const float*)d_in[7];
    const float* Wo  = (const float*)d_in[8];
    const float* bo  = (const float*)d_in[9];
    float* out = (float*)d_out;

    void *pq, *pk, *pv, *pc;
    cudaGetSymbolAddress(&pq, g_q);
    cudaGetSymbolAddress(&pk, g_k);
    cudaGetSymbolAddress(&pv, g_v);
    cudaGetSymbolAddress(&pc, g_ctx);

    const dim3 blk(256);

    qkv_proj<<<dim3(H_ / 128, (B_ * SQ_) / 128, 3), blk>>>(
        xq, xkv, Wq, bq, Wk, Wv, bv, (float*)pq, (float*)pk, (float*)pv);

    const int smem_bytes = (64 * 68 * 3 + 64 * 72 + 128 + 128 + 192) * (int)sizeof(float);
    cudaFuncSetAttribute(flash_mma, cudaFuncAttributeMaxDynamicSharedMemorySize, smem_bytes);
    flash_mma<<<dim3(SQ_ / 64, NH_, B_), blk, smem_bytes>>>(msk);

    out_proj<<<dim3(H_ / 128, (B_ * SQ_) / 128), blk>>>((const float*)pc, Wo, bo, out);
}

// round 5
// speedup vs baseline: 2.5577x; 1.0695x over previous
#include <cuda_runtime.h>

constexpr int B_   = 2;
constexpr int SQ_  = 2048;
constexpr int SKV_ = 2048;
constexpr int H_   = 1024;
constexpr int NH_  = 16;
constexpr int HD_  = 64;

__device__ float g_q[(size_t)B_ * SQ_ * H_];
__device__ float g_k[(size_t)B_ * SKV_ * H_];
__device__ float g_v[(size_t)B_ * SKV_ * H_];
__device__ float g_ctx[(size_t)B_ * SQ_ * H_];

__device__ __forceinline__ unsigned f2tf(float f) {
    unsigned u; asm("cvt.rna.tf32.f32 %0, %1;" : "=r"(u) : "f"(f)); return u;
}
__device__ __forceinline__ void mma8(float d[4], const unsigned a[4], const unsigned b[2]) {
    asm volatile(
        "mma.sync.aligned.m16n8k8.row.col.f32.tf32.tf32.f32 "
        "{%0,%1,%2,%3},{%4,%5,%6,%7},{%8,%9},{%0,%1,%2,%3};"
        : "+f"(d[0]), "+f"(d[1]), "+f"(d[2]), "+f"(d[3])
        : "r"(a[0]), "r"(a[1]), "r"(a[2]), "r"(a[3]), "r"(b[0]), "r"(b[1]));
}

// ---------------- projection GEMM (unchanged, known-good) ------------------
__device__ __forceinline__ void gemm_body(
    const float* __restrict__ A, const float* __restrict__ W,
    const float* __restrict__ bias, float* __restrict__ C,
    int M, int N, int K)
{
    __shared__ unsigned As[2][128][20];
    __shared__ unsigned Bs[2][128][20];

    const int tid = threadIdx.x;
    const int wid = tid >> 5, lane = tid & 31;
    const int g = lane >> 2, tg = lane & 3;
    const int wm = wid >> 2, wn = wid & 3;
    const int m0 = blockIdx.y << 7, n0 = blockIdx.x << 7;
    const int lrow = tid >> 1;
    const int lk   = (tid & 1) << 3;

    const float* Ap = A + (size_t)(m0 + lrow) * K + lk;
    const float* Wp = W + (size_t)(n0 + lrow) * K + lk;

    float acc[4][4][4] = {};
    float4 a0v = *(const float4*)Ap, a1v = *(const float4*)(Ap + 4);
    float4 b0v = *(const float4*)Wp, b1v = *(const float4*)(Wp + 4);
    {
        unsigned* ar = &As[0][lrow][lk];
        ar[0]=f2tf(a0v.x); ar[1]=f2tf(a0v.y); ar[2]=f2tf(a0v.z); ar[3]=f2tf(a0v.w);
        ar[4]=f2tf(a1v.x); ar[5]=f2tf(a1v.y); ar[6]=f2tf(a1v.z); ar[7]=f2tf(a1v.w);
        unsigned* br = &Bs[0][lrow][lk];
        br[0]=f2tf(b0v.x); br[1]=f2tf(b0v.y); br[2]=f2tf(b0v.z); br[3]=f2tf(b0v.w);
        br[4]=f2tf(b1v.x); br[5]=f2tf(b1v.y); br[6]=f2tf(b1v.z); br[7]=f2tf(b1v.w);
    }
    __syncthreads();

    const int NT = K >> 4;
    for (int kt = 0; kt < NT; kt++) {
        if (kt + 1 < NT) {
            const float* Ap2 = Ap + (kt + 1) * 16;
            const float* Wp2 = Wp + (kt + 1) * 16;
            a0v = *(const float4*)Ap2; a1v = *(const float4*)(Ap2 + 4);
            b0v = *(const float4*)Wp2; b1v = *(const float4*)(Wp2 + 4);
        }
        const int buf = kt & 1;
        #pragma unroll
        for (int ks = 0; ks < 2; ks++) {
            const int kk = ks << 3;
            unsigned bf[4][2];
            #pragma unroll
            for (int ni = 0; ni < 4; ni++) {
                const int col = (wn << 5) + (ni << 3) + g;
                bf[ni][0] = Bs[buf][col][kk + tg];
                bf[ni][1] = Bs[buf][col][kk + tg + 4];
            }
            #pragma unroll
            for (int mi = 0; mi < 4; mi++) {
                const int row = (wm << 6) + (mi << 4);
                unsigned af[4];
                af[0] = As[buf][row + g    ][kk + tg];
                af[1] = As[buf][row + g + 8][kk + tg];
                af[2] = As[buf][row + g    ][kk + tg + 4];
                af[3] = As[buf][row + g + 8][kk + tg + 4];
                #pragma unroll
                for (int ni = 0; ni < 4; ni++) mma8(acc[mi][ni], af, bf[ni]);
            }
        }
        if (kt + 1 < NT) {
            unsigned* ar = &As[buf ^ 1][lrow][lk];
            ar[0]=f2tf(a0v.x); ar[1]=f2tf(a0v.y); ar[2]=f2tf(a0v.z); ar[3]=f2tf(a0v.w);
            ar[4]=f2tf(a1v.x); ar[5]=f2tf(a1v.y); ar[6]=f2tf(a1v.z); ar[7]=f2tf(a1v.w);
            unsigned* br = &Bs[buf ^ 1][lrow][lk];
            br[0]=f2tf(b0v.x); br[1]=f2tf(b0v.y); br[2]=f2tf(b0v.z); br[3]=f2tf(b0v.w);
            br[4]=f2tf(b1v.x); br[5]=f2tf(b1v.y); br[6]=f2tf(b1v.z); br[7]=f2tf(b1v.w);
        }
        __syncthreads();
    }

    #pragma unroll
    for (int mi = 0; mi < 4; mi++) {
        const int r = m0 + (wm << 6) + (mi << 4) + g;
        #pragma unroll
        for (int ni = 0; ni < 4; ni++) {
            const int c = n0 + (wn << 5) + (ni << 3) + (tg << 1);
            float bx = 0.f, by = 0.f;
            if (bias) { bx = bias[c]; by = bias[c + 1]; }
            *(float2*)(C + (size_t)r * N + c) =
                make_float2(acc[mi][ni][0] + bx, acc[mi][ni][1] + by);
            *(float2*)(C + (size_t)(r + 8) * N + c) =
                make_float2(acc[mi][ni][2] + bx, acc[mi][ni][3] + by);
        }
    }
}

__global__ __launch_bounds__(256) void qkv_proj(
    const float* __restrict__ xq, const float* __restrict__ xkv,
    const float* __restrict__ Wq, const float* __restrict__ bq,
    const float* __restrict__ Wk,
    const float* __restrict__ Wv, const float* __restrict__ bv,
    float* __restrict__ q, float* __restrict__ k, float* __restrict__ v)
{
    const int z = blockIdx.z;
    const float* A    = (z == 0) ? xq : xkv;
    const float* W    = (z == 0) ? Wq : (z == 1 ? Wk : Wv);
    const float* bias = (z == 0) ? bq : (z == 1 ? nullptr : bv);
    float* C          = (z == 0) ? q  : (z == 1 ? k  : v);
    gemm_body(A, W, bias, C, B_ * SQ_, H_, H_);
}

__global__ __launch_bounds__(256) void out_proj(
    const float* __restrict__ ctx, const float* __restrict__ Wo,
    const float* __restrict__ bo, float* __restrict__ out)
{
    gemm_body(ctx, Wo, bo, out, B_ * SQ_, H_, H_);
}

// ---------------------------------------------------------------------------
// Flash v2: BQ=128, 8 warps, warp owns 16 rows x 64 cols.
// Warp-local softmax (shfl only), warp-private P smem, m/l in registers.
// ---------------------------------------------------------------------------
constexpr int FLASH_SMEM = (128 * 68 + 64 * 68 + 64 * 72 + 8 * 16 * 68) * 4;

__global__ __launch_bounds__(256, 2) void flash_mma2(const float* __restrict__ mask)
{
    extern __shared__ unsigned fsm[];
    unsigned (*Qs)[68] = (unsigned(*)[68])fsm;                       // [128][68]
    unsigned (*Ks)[68] = (unsigned(*)[68])(fsm + 128 * 68);          // [64][68]
    unsigned (*Vs)[72] = (unsigned(*)[72])(fsm + 128 * 68 + 64 * 68);// [64][72]
    unsigned* Pbase = fsm + 128 * 68 + 64 * 68 + 64 * 72;            // 8 x [16][68]

    const int tid = threadIdx.x, wid = tid >> 5, lane = tid & 31;
    const int g = lane >> 2, tg = lane & 3;
    const int r0 = wid << 4;
    const int q0 = blockIdx.x << 7, h = blockIdx.y, b = blockIdx.z;

    const float* Qg = g_q + (size_t)(b * SQ_ + q0) * H_ + h * HD_;
    const float* Kg = g_k + (size_t)b * SKV_ * H_ + h * HD_;
    const float* Vg = g_v + (size_t)b * SKV_ * H_ + h * HD_;
    const float* Mg = mask + (size_t)(b * SQ_ + q0) * SKV_;
    unsigned (*Pw)[68] = (unsigned(*)[68])(Pbase + wid * (16 * 68));

    // stage Q (tf32, pre-scaled by 1/8) once
    #pragma unroll
    for (int i = 0; i < 8; i++) {
        const int idx = tid + (i << 8);
        const int r = idx >> 4, d = (idx & 15) << 2;
        const float4 v = *(const float4*)(Qg + (size_t)r * H_ + d);
        *(uint4*)&Qs[r][d] = make_uint4(f2tf(v.x * 0.125f), f2tf(v.y * 0.125f),
                                        f2tf(v.z * 0.125f), f2tf(v.w * 0.125f));
    }

    float mr0 = -1e30f, mr1 = -1e30f, lr0 = 0.f, lr1 = 0.f;
    float o[8][4] = {};

    for (int kv0 = 0; kv0 < SKV_; kv0 += 64) {
        __syncthreads();                      // K/V consumed (also covers Q stage)
        #pragma unroll
        for (int i = 0; i < 4; i++) {
            const int idx = tid + (i << 8);
            const int c = idx >> 4, d = (idx & 15) << 2;
            const float4 kv = *(const float4*)(Kg + (size_t)(kv0 + c) * H_ + d);
            *(uint4*)&Ks[c][d] = make_uint4(f2tf(kv.x), f2tf(kv.y), f2tf(kv.z), f2tf(kv.w));
            const float4 vv = *(const float4*)(Vg + (size_t)(kv0 + c) * H_ + d);
            *(uint4*)&Vs[c][d] = make_uint4(f2tf(vv.x), f2tf(vv.y), f2tf(vv.z), f2tf(vv.w));
        }
        __syncthreads();

        // S = Q @ K^T  (warp rows r0..r0+15, all 64 cols)
        float s[8][4] = {};
        #pragma unroll
        for (int ks = 0; ks < 8; ks++) {
            const int kk = ks << 3;
            unsigned af[4];
            af[0] = Qs[r0 + g    ][kk + tg];
            af[1] = Qs[r0 + g + 8][kk + tg];
            af[2] = Qs[r0 + g    ][kk + tg + 4];
            af[3] = Qs[r0 + g + 8][kk + tg + 4];
            #pragma unroll
            for (int ni = 0; ni < 8; ni++) {
                const int c = (ni << 3) + g;
                unsigned bf[2] = { Ks[c][kk + tg], Ks[c][kk + tg + 4] };
                mma8(s[ni], af, bf);
            }
        }

        // mask + warp-local row max (rows r0+g, r0+g+8)
        float tm0 = -1e30f, tm1 = -1e30f;
        #pragma unroll
        for (int ni = 0; ni < 8; ni++) {
            const int c = (ni << 3) + (tg << 1);
            const float2 mv0 = *(const float2*)(Mg + (size_t)(r0 + g) * SKV_ + kv0 + c);
            const float2 mv1 = *(const float2*)(Mg + (size_t)(r0 + g + 8) * SKV_ + kv0 + c);
            s[ni][0] += (mv0.x - 1.f) * 10000.f;
            s[ni][1] += (mv0.y - 1.f) * 10000.f;
            s[ni][2] += (mv1.x - 1.f) * 10000.f;
            s[ni][3] += (mv1.y - 1.f) * 10000.f;
            tm0 = fmaxf(tm0, fmaxf(s[ni][0], s[ni][1]));
            tm1 = fmaxf(tm1, fmaxf(s[ni][2], s[ni][3]));
        }
        tm0 = fmaxf(tm0, __shfl_xor_sync(~0u, tm0, 1));
        tm0 = fmaxf(tm0, __shfl_xor_sync(~0u, tm0, 2));
        tm1 = fmaxf(tm1, __shfl_xor_sync(~0u, tm1, 1));
        tm1 = fmaxf(tm1, __shfl_xor_sync(~0u, tm1, 2));

        const float mn0 = fmaxf(mr0, tm0), mn1 = fmaxf(mr1, tm1);
        const float al0 = __expf(mr0 - mn0), al1 = __expf(mr1 - mn1);
        mr0 = mn0; mr1 = mn1;

        float ps0 = 0.f, ps1 = 0.f;
        #pragma unroll
        for (int ni = 0; ni < 8; ni++) {
            const int c = (ni << 3) + (tg << 1);
            const float p00 = __expf(s[ni][0] - mn0), p01 = __expf(s[ni][1] - mn0);
            const float p10 = __expf(s[ni][2] - mn1), p11 = __expf(s[ni][3] - mn1);
            ps0 += p00 + p01; ps1 += p10 + p11;
            Pw[g    ][c] = f2tf(p00); Pw[g    ][c + 1] = f2tf(p01);
            Pw[g + 8][c] = f2tf(p10); Pw[g + 8][c + 1] = f2tf(p11);
            o[ni][0] *= al0; o[ni][1] *= al0; o[ni][2] *= al1; o[ni][3] *= al1;
        }
        ps0 += __shfl_xor_sync(~0u, ps0, 1); ps0 += __shfl_xor_sync(~0u, ps0, 2);
        ps1 += __shfl_xor_sync(~0u, ps1, 1); ps1 += __shfl_xor_sync(~0u, ps1, 2);
        lr0 = lr0 * al0 + ps0;
        lr1 = lr1 * al1 + ps1;
        __syncwarp();

        // O += P @ V  (head-dim cols = 64)
        #pragma unroll
        for (int ks = 0; ks < 8; ks++) {
            const int kk = ks << 3;
            unsigned af[4];
            af[0] = Pw[g    ][kk + tg];
            af[1] = Pw[g + 8][kk + tg];
            af[2] = Pw[g    ][kk + tg + 4];
            af[3] = Pw[g + 8][kk + tg + 4];
            #pragma unroll
            for (int ni = 0; ni < 8; ni++) {
                const int e = (ni << 3) + g;
                unsigned bf[2] = { Vs[kk + tg][e], Vs[kk + tg + 4][e] };
                mma8(o[ni], af, bf);
            }
        }
        __syncwarp();   // P reads done before next-tile P writes
    }

    float* Og = g_ctx + (size_t)(b * SQ_ + q0) * H_ + h * HD_;
    const float inv0 = 1.f / lr0, inv1 = 1.f / lr1;
    #pragma unroll
    for (int ni = 0; ni < 8; ni++) {
        const int c = (ni << 3) + (tg << 1);
        *(float2*)(Og + (size_t)(r0 + g) * H_ + c) =
            make_float2(o[ni][0] * inv0, o[ni][1] * inv0);
        *(float2*)(Og + (size_t)(r0 + g + 8) * H_ + c) =
            make_float2(o[ni][2] * inv1, o[ni][3] * inv1);
    }
}

// ---------------------------------------------------------------------------
extern "C" void kernel_launch(void* const* d_in, const int* in_sizes, int n_in,
                              void* d_out, int out_size)
{
    const float* xq  = (const float*)d_in[0];
    const float* xkv = (const float*)d_in[1];
    const float* msk = (const float*)d_in[2];
    const float* Wq  = (const float*)d_in[3];
    const float* bq  = (const float*)d_in[4];
    const float* Wk  = (const float*)d_in[5];
    const float* Wv  = (const float*)d_in[6];
    const float* bv  = (const float*)d_in[7];
    const float* Wo  = (const float*)d_in[8];
    const float* bo  = (const float*)d_in[9];
    float* out = (float*)d_out;

    void *pq, *pk, *pv, *pc;
    cudaGetSymbolAddress(&pq, g_q);
    cudaGetSymbolAddress(&pk, g_k);
    cudaGetSymbolAddress(&pv, g_v);
    cudaGetSymbolAddress(&pc, g_ctx);

    const dim3 blk(256);

    qkv_proj<<<dim3(H_ / 128, (B_ * SQ_) / 128, 3), blk>>>(
        xq, xkv, Wq, bq, Wk, Wv, bv, (float*)pq, (float*)pk, (float*)pv);

    cudaFuncSetAttribute(flash_mma2, cudaFuncAttributeMaxDynamicSharedMemorySize, FLASH_SMEM);
    flash_mma2<<<dim3(SQ_ / 128, NH_, B_), blk, FLASH_SMEM>>>(msk);

    out_proj<<<dim3(H_ / 128, (B_ * SQ_) / 128), blk>>>((const float*)pc, Wo, bo, out);
}